// round 16
// baseline (speedup 1.0000x reference)
#include <cuda_runtime.h>
#include <math.h>
#include <float.h>

// ---------------------------------------------------------------------------
// MultiLatentSpaceSimilarity — fp32 f32x2, 8x4 tiles, 3 CTAs/SM.
// R14 structure (one launch per phase, all groups, fp32 E — bf16 E broke
// argmax in R15, heat path needs fp32). Out s-split reduced 4->2:
// halves g_outp round-trip, grid 3072 = 6.92 waves (clean quantization).
// (tcgen05 unavailable: harness PTX target is sm_103, no 'a' features.)
// B=16, C=256, S=1024, 3 groups x 8 splits, L=64, HEADS=8, DH=64, INNER=512
// ---------------------------------------------------------------------------

constexpr int B_ = 16, C_ = 256, S_ = 1024;
constexpr int SPLITS_ = 8, L_ = 64, HEADS_ = 8, DH_ = 64, INNER_ = 512;
constexpr int G_ = 3;
constexpr float SCALE_ = 0.125f;

constexpr size_t K_GSTRIDE  = (size_t)B_ * INNER_ * S_;
constexpr size_t V_GSTRIDE  = (size_t)B_ * S_ * INNER_;
constexpr size_t Q_GSTRIDE  = (size_t)SPLITS_ * L_ * INNER_;
constexpr size_t E_GSTRIDE  = (size_t)B_ * HEADS_ * SPLITS_ * L_ * S_;
constexpr size_t ZP_GSTRIDE = (size_t)B_ * HEADS_ * SPLITS_ * 8 * L_;
constexpr size_t IZ_GSTRIDE = (size_t)B_ * HEADS_ * SPLITS_ * L_;
constexpr size_t OP_GSTRIDE = (size_t)2 * 128 * 4 * 64 * 128;   // sz=2 now
constexpr size_t HP_GSTRIDE = (size_t)B_ * SPLITS_ * HEADS_ * S_;

__device__ float g_K[G_ * K_GSTRIDE];     // [g][b][h*64+d][s]
__device__ float g_V[G_ * V_GSTRIDE];     // [g][b][s][h*64+d]
__device__ float g_Q[G_ * Q_GSTRIDE];     // [g][p][l][n]
__device__ float g_E[G_ * E_GSTRIDE];     // [g][bhp][l][s]  fp32 (required)
__device__ float g_Zp[G_ * ZP_GSTRIDE];
__device__ float g_invZ[G_ * IZ_GSTRIDE];
__device__ float g_outp[G_ * OP_GSTRIDE]; // [g][sz][bh][rowG][d][row]
__device__ float g_heatp[G_ * HP_GSTRIDE];// [g][bp][h][s]
__device__ float g_distp[G_ * B_ * HEADS_ * SPLITS_];

typedef unsigned long long ull;

__device__ __forceinline__ void ffma2(ull& d, ull a, ull b)
{
    asm("fma.rn.f32x2 %0, %1, %2, %0;" : "+l"(d) : "l"(a), "l"(b));
}
__device__ __forceinline__ float2 unpk(ull v)
{
    float2 r;
    asm("mov.b64 {%0, %1}, %2;" : "=f"(r.x), "=f"(r.y) : "l"(v));
    return r;
}
__device__ __forceinline__ ull pack2(float v)
{
    ull r;
    asm("mov.b64 %0, {%1, %1};" : "=l"(r) : "f"(v));
    return r;
}
__device__ __forceinline__ void ld_bcast4(const float* p, ull* w)
{
    float4 b = *(const float4*)p;
    w[0] = pack2(b.x); w[1] = pack2(b.y); w[2] = pack2(b.z); w[3] = pack2(b.w);
}

// cp.async helpers
__device__ __forceinline__ void cpa16(void* smem, const void* g)
{
    unsigned a = (unsigned)__cvta_generic_to_shared(smem);
    asm volatile("cp.async.cg.shared.global [%0], [%1], 16;\n" :: "r"(a), "l"(g));
}
__device__ __forceinline__ void cpa_commit()
{
    asm volatile("cp.async.commit_group;\n");
}
__device__ __forceinline__ void cpa_wait1()
{
    asm volatile("cp.async.wait_group 1;\n");
}
__device__ __forceinline__ void cpa_wait0()
{
    asm volatile("cp.async.wait_group 0;\n");
}

// ---------------------------------------------------------------------------
// K/V projection, all groups + both dsts in one launch.
// blockIdx.z = g*32 + dst*16 + batch. DST 0: K[g][b][n][m]. 1: V[g][b][m][n].
// ---------------------------------------------------------------------------
__global__ __launch_bounds__(256, 3) void projKV_kernel(
    const float* __restrict__ A, const float* __restrict__ Wk,
    const float* __restrict__ Wv)
{
    extern __shared__ float sm[];
    float* As = sm;                  // [2][32][128]
    float* Ws = sm + 2 * 32 * 128;   // [2][32][68]

    int tid = threadIdx.x;
    int tx = tid & 31, wy = tid >> 5;
    int m0 = blockIdx.x * 128, n0 = blockIdx.y * 64;
    int z = blockIdx.z;
    int g = z >> 5, r = z & 31;
    int dst = r >> 4, batch = r & 15;
    const float* W = (dst ? Wv : Wk) + (size_t)g * C_ * INNER_;
    const float* Ab = A + (size_t)batch * C_ * S_;

    ull acc[8][2] = {};
    for (int t = 0; t < 9; t++) {
        if (t < 8) {
            float* as = As + (t & 1) * 32 * 128;
            float* ws = Ws + (t & 1) * 32 * 68;
            int c0 = t * 32;
            #pragma unroll
            for (int it = 0; it < 4; it++) {
                int idx = tid + it * 256;
                int c = idx >> 5, f4 = idx & 31;
                cpa16(&as[c * 128 + f4 * 4],
                      &Ab[(size_t)(c0 + c) * S_ + m0 + f4 * 4]);
            }
            #pragma unroll
            for (int it = 0; it < 2; it++) {
                int idx = tid + it * 256;
                int c = idx >> 4, f4 = idx & 15;
                cpa16(&ws[c * 68 + f4 * 4],
                      &W[(size_t)(c0 + c) * INNER_ + n0 + f4 * 4]);
            }
            cpa_commit();
        }
        if (t == 0) continue;
        if (t < 8) cpa_wait1(); else cpa_wait0();
        __syncthreads();
        const float* as = As + ((t - 1) & 1) * 32 * 128;
        const float* ws = Ws + ((t - 1) & 1) * 32 * 68;
        #pragma unroll 4
        for (int c = 0; c < 32; c++) {
            ulonglong2 av = *(const ulonglong2*)&as[c * 128 + tx * 4];
            ull wp[4];
            ld_bcast4(&ws[c * 68 + wy * 8], wp);
            #pragma unroll
            for (int ni = 0; ni < 4; ni++) {
                ffma2(acc[ni][0], wp[ni], av.x);
                ffma2(acc[ni][1], wp[ni], av.y);
            }
            ld_bcast4(&ws[c * 68 + wy * 8 + 4], wp);
            #pragma unroll
            for (int ni = 0; ni < 4; ni++) {
                ffma2(acc[4 + ni][0], wp[ni], av.x);
                ffma2(acc[4 + ni][1], wp[ni], av.y);
            }
        }
        if (t < 8) __syncthreads();
    }

    if (dst == 0) {
        float* kg = g_K + (size_t)g * K_GSTRIDE;
        #pragma unroll
        for (int ni = 0; ni < 8; ni++) {
            int n = n0 + wy * 8 + ni;
            float2 f0 = unpk(acc[ni][0]), f1 = unpk(acc[ni][1]);
            *(float4*)&kg[((size_t)batch * INNER_ + n) * S_ + m0 + tx * 4] =
                make_float4(f0.x, f0.y, f1.x, f1.y);
        }
    } else {
        float* vg = g_V + (size_t)g * V_GSTRIDE;
        #pragma unroll
        for (int j = 0; j < 4; j++) {
            int m = m0 + tx * 4 + j;
            int sj = j >> 1, hi = j & 1;
            float v[8];
            #pragma unroll
            for (int ni = 0; ni < 8; ni++) {
                float2 f = unpk(acc[ni][sj]);
                v[ni] = hi ? f.y : f.x;
            }
            float* vr = &vg[((size_t)batch * S_ + m) * INNER_ + n0 + wy * 8];
            *(float4*)&vr[0] = make_float4(v[0], v[1], v[2], v[3]);
            *(float4*)&vr[4] = make_float4(v[4], v[5], v[6], v[7]);
        }
    }
}

// ---------------------------------------------------------------------------
// Q projection, all groups: blockIdx.z = g*8 + p. out g_Q[g][p][l][n]
// ---------------------------------------------------------------------------
__global__ void projQ_kernel(const float* __restrict__ protos,
                             const float* __restrict__ Wq)
{
    __shared__ __align__(16) float As[32][68];
    __shared__ __align__(16) float Wd[32][132];
    int tid = threadIdx.x;
    int txq = tid & 15, tyq = tid >> 4;
    int n0 = blockIdx.y * 64;
    int z = blockIdx.z;
    int g = z >> 3, p = z & 7;
    const float* Ab = protos + (size_t)(g * SPLITS_ + p) * C_ * L_;
    const float* W = Wq + (size_t)g * C_ * INNER_;
    float* qg = g_Q + (size_t)g * Q_GSTRIDE;

    ull acc[4][2] = {};
    for (int c0 = 0; c0 < C_; c0 += 32) {
        __syncthreads();
        for (int idx = tid; idx < 512; idx += 256) {
            int c = idx >> 4, q = idx & 15;
            *(float4*)&As[c][q * 4] =
                *(const float4*)&Ab[(size_t)(c0 + c) * L_ + q * 4];
            float4 w = *(const float4*)&W[(size_t)(c0 + c) * INNER_ + n0 + q * 4];
            Wd[c][q * 8 + 0] = w.x; Wd[c][q * 8 + 1] = w.x;
            Wd[c][q * 8 + 2] = w.y; Wd[c][q * 8 + 3] = w.y;
            Wd[c][q * 8 + 4] = w.z; Wd[c][q * 8 + 5] = w.z;
            Wd[c][q * 8 + 6] = w.w; Wd[c][q * 8 + 7] = w.w;
        }
        __syncthreads();
        #pragma unroll
        for (int cc = 0; cc < 32; cc++) {
            ulonglong2 am  = *(ulonglong2*)&As[cc][txq * 4];
            ulonglong2 w01 = *(ulonglong2*)&Wd[cc][tyq * 8];
            ulonglong2 w23 = *(ulonglong2*)&Wd[cc][tyq * 8 + 4];
            ffma2(acc[0][0], w01.x, am.x); ffma2(acc[0][1], w01.x, am.y);
            ffma2(acc[1][0], w01.y, am.x); ffma2(acc[1][1], w01.y, am.y);
            ffma2(acc[2][0], w23.x, am.x); ffma2(acc[2][1], w23.x, am.y);
            ffma2(acc[3][0], w23.y, am.x); ffma2(acc[3][1], w23.y, am.y);
        }
    }
    #pragma unroll
    for (int i4 = 0; i4 < 4; i4++) {
        int n = n0 + tyq * 4 + i4;
        float2 a = unpk(acc[i4][0]), b2 = unpk(acc[i4][1]);
        int l = txq * 4;
        qg[((size_t)p * L_ + l + 0) * INNER_ + n] = a.x;
        qg[((size_t)p * L_ + l + 1) * INNER_ + n] = a.y;
        qg[((size_t)p * L_ + l + 2) * INNER_ + n] = b2.x;
        qg[((size_t)p * L_ + l + 3) * INNER_ + n] = b2.y;
    }
}

// ---------------------------------------------------------------------------
// Scores, all groups: blockIdx.y = g*1024 + bhp. Grid (8, 3072).
// ---------------------------------------------------------------------------
__global__ __launch_bounds__(256, 3) void scores_kernel()
{
    extern __shared__ float sm[];
    float* Kt = sm;                  // [2][32][128]
    float* Qs = sm + 2 * 32 * 128;   // [64][68]  Qs[d][l]

    int sq = blockIdx.x;
    int y = blockIdx.y;
    int g = y >> 10, bhp = y & 1023;
    int p = bhp & 7, h = (bhp >> 3) & 7, b = bhp >> 6;
    int s0 = sq * 128;
    int tid = threadIdx.x;
    int tx = tid & 31, wy = tid >> 5;

    const float* kbase = g_K + (size_t)g * K_GSTRIDE +
                         ((size_t)(b * HEADS_ + h) * DH_) * S_ + s0;
    const float* qbase = g_Q + (size_t)g * Q_GSTRIDE +
                         (size_t)p * L_ * INNER_ + h * DH_;

    #pragma unroll
    for (int t = 0; t < 2; t++) {
        float* kt = Kt + t * 32 * 128;
        #pragma unroll
        for (int it = 0; it < 4; it++) {
            int idx = tid + it * 256;
            int d = idx >> 5, f4 = idx & 31;
            cpa16(&kt[d * 128 + f4 * 4],
                  &kbase[(size_t)(t * 32 + d) * S_ + f4 * 4]);
        }
        cpa_commit();
    }

    #pragma unroll
    for (int it = 0; it < 4; it++) {
        int idx = tid + it * 256;
        int dq = idx & 15, l = idx >> 4;
        float4 q = *(const float4*)&qbase[(size_t)l * INNER_ + dq * 4];
        Qs[(dq * 4 + 0) * 68 + l] = q.x;
        Qs[(dq * 4 + 1) * 68 + l] = q.y;
        Qs[(dq * 4 + 2) * 68 + l] = q.z;
        Qs[(dq * 4 + 3) * 68 + l] = q.w;
    }

    ull acc[8][2] = {};
    #pragma unroll
    for (int t = 0; t < 2; t++) {
        if (t == 0) cpa_wait1(); else cpa_wait0();
        __syncthreads();
        const float* kt = Kt + t * 32 * 128;
        #pragma unroll 4
        for (int d = 0; d < 32; d++) {
            ulonglong2 kv = *(const ulonglong2*)&kt[d * 128 + tx * 4];
            ull qp[4];
            ld_bcast4(&Qs[(t * 32 + d) * 68 + wy * 8], qp);
            #pragma unroll
            for (int li = 0; li < 4; li++) {
                ffma2(acc[li][0], qp[li], kv.x);
                ffma2(acc[li][1], qp[li], kv.y);
            }
            ld_bcast4(&Qs[(t * 32 + d) * 68 + wy * 8 + 4], qp);
            #pragma unroll
            for (int li = 0; li < 4; li++) {
                ffma2(acc[4 + li][0], qp[li], kv.x);
                ffma2(acc[4 + li][1], qp[li], kv.y);
            }
        }
    }

    float* eg = g_E + (size_t)g * E_GSTRIDE;
    float* zg = g_Zp + (size_t)g * ZP_GSTRIDE;
    #pragma unroll
    for (int li = 0; li < 8; li++) {
        int l = wy * 8 + li;
        float2 a0 = unpk(acc[li][0]), a1 = unpk(acc[li][1]);
        float e0 = __expf(a0.x * SCALE_), e1 = __expf(a0.y * SCALE_);
        float e2 = __expf(a1.x * SCALE_), e3 = __expf(a1.y * SCALE_);
        *(float4*)&eg[((size_t)bhp * L_ + l) * S_ + s0 + tx * 4] =
            make_float4(e0, e1, e2, e3);
        float z = (e0 + e1) + (e2 + e3);
        #pragma unroll
        for (int off = 16; off; off >>= 1)
            z += __shfl_xor_sync(0xffffffffu, z, off);
        if (tx == 0) zg[(bhp * 8 + sq) * 64 + l] = z;
    }
}

// ---------------------------------------------------------------------------
__global__ void invz_kernel()   // 3 groups: 196608 elements
{
    int i = blockIdx.x * 256 + threadIdx.x;
    int bhp_g = i >> 6, l = i & 63;
    float z = 0.f;
    #pragma unroll
    for (int j = 0; j < 8; j++) z += g_Zp[((size_t)bhp_g * 8 + j) * 64 + l];
    g_invZ[i] = 1.0f / z;
}

// ---------------------------------------------------------------------------
// Out slices, all groups: blockIdx = (rowG 4, sz 2, g*128+bh). 3072 CTAs.
// Each CTA covers 512 s in 16 chunks of 32.
// ---------------------------------------------------------------------------
__global__ __launch_bounds__(256, 3) void out_slice_kernel()
{
    extern __shared__ float sm[];
    float* Es    = sm;                       // [32][132]  Es[s][row]
    float* Vs    = sm + 32 * 132;            // [32][68]   Vs[s][d]
    float* invZs = sm + 32 * 132 + 32 * 68;  // [128]

    int rowG = blockIdx.x;
    int sz   = blockIdx.y;                   // 0..1
    int zz   = blockIdx.z;
    int g = zz >> 7, bh = zz & 127;
    int b = bh >> 3, h = bh & 7;
    int tid = threadIdx.x;
    int tx = tid & 31, wy = tid >> 5;

    if (tid < 128)
        invZs[tid] = g_invZ[(size_t)g * IZ_GSTRIDE +
                            (bh * 8 + rowG * 2) * 64 + tid];

    const float* vbase = g_V + (size_t)g * V_GSTRIDE +
                         (size_t)b * S_ * INNER_ + h * DH_;
    size_t ebase = (size_t)g * E_GSTRIDE +
                   (size_t)(bh * 8 + rowG * 2) * L_ * S_;

    ull acc[8][2] = {};
    for (int c = 0; c < 16; c++) {
        int s0 = sz * 512 + c * 32;
        __syncthreads();
        #pragma unroll
        for (int it = 0; it < 2; it++) {
            int idx = tid + it * 256;
            int f4 = idx & 15, s = idx >> 4;
            cpa16(&Vs[s * 68 + f4 * 4],
                  &vbase[(size_t)(s0 + s) * INNER_ + f4 * 4]);
        }
        cpa_commit();
        #pragma unroll
        for (int it = 0; it < 4; it++) {
            int idx = tid + it * 256;
            int sq4 = idx & 7, r = idx >> 3;
            float4 e = *(const float4*)&g_E[ebase + (size_t)r * S_ + s0 + sq4 * 4];
            Es[(sq4 * 4 + 0) * 132 + r] = e.x;
            Es[(sq4 * 4 + 1) * 132 + r] = e.y;
            Es[(sq4 * 4 + 2) * 132 + r] = e.z;
            Es[(sq4 * 4 + 3) * 132 + r] = e.w;
        }
        cpa_wait0();
        __syncthreads();

        #pragma unroll 4
        for (int s = 0; s < 32; s++) {
            ulonglong2 ev = *(const ulonglong2*)&Es[s * 132 + tx * 4];
            ull vp[4];
            ld_bcast4(&Vs[s * 68 + wy * 8], vp);
            #pragma unroll
            for (int di = 0; di < 4; di++) {
                ffma2(acc[di][0], vp[di], ev.x);
                ffma2(acc[di][1], vp[di], ev.y);
            }
            ld_bcast4(&Vs[s * 68 + wy * 8 + 4], vp);
            #pragma unroll
            for (int di = 0; di < 4; di++) {
                ffma2(acc[4 + di][0], vp[di], ev.x);
                ffma2(acc[4 + di][1], vp[di], ev.y);
            }
        }

        if (tid < 64) {
            int s_loc = tid & 31, p_loc = tid >> 5;
            float hacc = 0.f;
            #pragma unroll 16
            for (int l = 0; l < 64; l++)
                hacc += Es[s_loc * 132 + p_loc * 64 + l] * invZs[p_loc * 64 + l];
            int p = rowG * 2 + p_loc;
            g_heatp[(size_t)g * HP_GSTRIDE +
                    ((size_t)(b * SPLITS_ + p) * HEADS_ + h) * S_ + s0 + s_loc] = hacc;
        }
    }

    float* outBase = g_outp + (size_t)g * OP_GSTRIDE +
        (((size_t)(sz * 128 + bh) * 4 + rowG) * 64) * 128;
    #pragma unroll
    for (int di = 0; di < 8; di++) {
        int d = wy * 8 + di;
        float2 f0 = unpk(acc[di][0]), f1 = unpk(acc[di][1]);
        *(float4*)&outBase[(size_t)d * 128 + tx * 4] =
            make_float4(f0.x, f0.y, f1.x, f1.y);
    }
}

// ---------------------------------------------------------------------------
// Finish, all groups: blockIdx.x = g*1024 + bhp. Sums 2 slice partials.
// ---------------------------------------------------------------------------
__global__ void finish_kernel()
{
    int bid = blockIdx.x;
    int g = bid >> 10, bhp = bid & 1023;
    int p = bhp & 7, h = (bhp >> 3) & 7, b = bhp >> 6;
    int bh = b * 8 + h;
    int rowG = p >> 1, p_loc = p & 1;
    int tid = threadIdx.x;

    const float* qb = g_Q + (size_t)g * Q_GSTRIDE +
                      (size_t)p * L_ * INNER_ + h * DH_;
    const float* op = g_outp + (size_t)g * OP_GSTRIDE;
    float ssum = 0.f;
    #pragma unroll
    for (int it = 0; it < 16; it++) {
        int idx = tid + it * 256;
        int d = idx >> 6, l = idx & 63;
        float v = 0.f;
        #pragma unroll
        for (int sz = 0; sz < 2; sz++)
            v += op[(((size_t)(sz * 128 + bh) * 4 + rowG) * 64 + d) * 128 +
                    p_loc * 64 + l];
        float o = v * g_invZ[(size_t)g * IZ_GSTRIDE + bhp * 64 + l];
        float diff = qb[(size_t)l * INNER_ + d] - o;
        ssum += diff * diff;
    }
    __shared__ float red[256];
    red[tid] = ssum;
    __syncthreads();
    for (int off = 128; off > 0; off >>= 1) {
        if (tid < off) red[tid] += red[tid + off];
        __syncthreads();
    }
    if (tid == 0) g_distp[bid] = red[0];
}

// ---------------------------------------------------------------------------
__global__ void reduce_dist_kernel(float* __restrict__ out)
{
    int g = blockIdx.x;
    int t = threadIdx.x;
    if (t < B_ * SPLITS_) {
        int p = t & 7, b = t >> 3;
        float s = 0.f;
        #pragma unroll
        for (int h = 0; h < HEADS_; h++)
            s += g_distp[g * 1024 + b * 64 + h * 8 + p];
        out[b * 24 + g * 8 + p] = s * (1.0f / (L_ * INNER_));
    }
}

__global__ void argmax_kernel(float* __restrict__ out)
{
    int bp = blockIdx.x;
    int g = blockIdx.y;
    int p = bp & 7, b = bp >> 3;
    const float* hp = g_heatp + (size_t)g * HP_GSTRIDE + (size_t)bp * HEADS_ * S_;
    int tid = threadIdx.x;

    float best = -FLT_MAX;
    int bidx = 0;
    for (int s = tid; s < S_; s += 256) {
        float v = 0.f;
        #pragma unroll
        for (int h = 0; h < HEADS_; h++) v += hp[(size_t)h * S_ + s];
        if (v > best) { best = v; bidx = s; }
    }
    __shared__ float sv[256];
    __shared__ int si[256];
    sv[tid] = best; si[tid] = bidx;
    __syncthreads();
    for (int off = 128; off > 0; off >>= 1) {
        if (tid < off) {
            bool take = (sv[tid + off] > sv[tid]) ||
                        (sv[tid + off] == sv[tid] && si[tid + off] < si[tid]);
            if (take) { sv[tid] = sv[tid + off]; si[tid] = si[tid + off]; }
        }
        __syncthreads();
    }
    if (tid == 0) out[384 + b * 24 + g * 8 + p] = (float)si[0];
}

// ---------------------------------------------------------------------------
extern "C" void kernel_launch(void* const* d_in, const int* in_sizes, int n_in,
                              void* d_out, int out_size)
{
    const float* x      = (const float*)d_in[0];
    const float* protos = (const float*)d_in[1];
    const float* Wq     = (const float*)d_in[2];
    const float* Wk     = (const float*)d_in[3];
    const float* Wv     = (const float*)d_in[4];
    float* out = (float*)d_out;

    constexpr int PROJ_SMEM   = (2 * 32 * 128 + 2 * 32 * 68) * 4;    // 50176
    constexpr int SCORES_SMEM = (2 * 32 * 128 + 64 * 68) * 4;        // 50176
    constexpr int OUT_SMEM    = (32 * 132 + 32 * 68 + 128) * 4;      // 26112

    cudaFuncSetAttribute(projKV_kernel,
                         cudaFuncAttributeMaxDynamicSharedMemorySize, PROJ_SMEM);
    cudaFuncSetAttribute(scores_kernel,
                         cudaFuncAttributeMaxDynamicSharedMemorySize, SCORES_SMEM);

    projKV_kernel<<<dim3(S_ / 128, INNER_ / 64, G_ * 32), 256, PROJ_SMEM>>>(
        x, Wk, Wv);
    projQ_kernel<<<dim3(1, INNER_ / 64, G_ * SPLITS_), 256>>>(protos, Wq);
    scores_kernel<<<dim3(8, G_ * 1024), 256, SCORES_SMEM>>>();
    invz_kernel<<<G_ * 256, 256>>>();
    out_slice_kernel<<<dim3(4, 2, G_ * 128), 256, OUT_SMEM>>>();
    finish_kernel<<<G_ * 1024, 256>>>();
    reduce_dist_kernel<<<G_, 128>>>(out);
    argmax_kernel<<<dim3(B_ * SPLITS_, G_), 256>>>(out);
}

// round 17
// speedup vs baseline: 1.0495x; 1.0495x over previous
#include <cuda_runtime.h>
#include <math.h>
#include <float.h>

// ---------------------------------------------------------------------------
// MultiLatentSpaceSimilarity — fp32 f32x2, 8x4 tiles, 3 CTAs/SM.
// R14 structure (sz=4 out split — R16 proved sz=2 trades parallelism for
// traffic and loses). Launch-graph diet: invz folded into consumers,
// projQ merged into proj launch, argmax merged into finish launch.
// 5 launches total. (tcgen05 unavailable: harness PTX target is sm_103.)
// B=16, C=256, S=1024, 3 groups x 8 splits, L=64, HEADS=8, DH=64, INNER=512
// ---------------------------------------------------------------------------

constexpr int B_ = 16, C_ = 256, S_ = 1024;
constexpr int SPLITS_ = 8, L_ = 64, HEADS_ = 8, DH_ = 64, INNER_ = 512;
constexpr int G_ = 3;
constexpr float SCALE_ = 0.125f;

constexpr size_t K_GSTRIDE  = (size_t)B_ * INNER_ * S_;
constexpr size_t V_GSTRIDE  = (size_t)B_ * S_ * INNER_;
constexpr size_t Q_GSTRIDE  = (size_t)SPLITS_ * L_ * INNER_;
constexpr size_t E_GSTRIDE  = (size_t)B_ * HEADS_ * SPLITS_ * L_ * S_;
constexpr size_t ZP_GSTRIDE = (size_t)B_ * HEADS_ * SPLITS_ * 8 * L_;
constexpr size_t OP_GSTRIDE = (size_t)4 * 128 * 4 * 64 * 128;
constexpr size_t HP_GSTRIDE = (size_t)B_ * SPLITS_ * HEADS_ * S_;

__device__ float g_K[G_ * K_GSTRIDE];     // [g][b][h*64+d][s]
__device__ float g_V[G_ * V_GSTRIDE];     // [g][b][s][h*64+d]
__device__ float g_Q[G_ * Q_GSTRIDE];     // [g][p][l][n]
__device__ float g_E[G_ * E_GSTRIDE];     // [g][bhp][l][s]  fp32 (argmax needs it)
__device__ float g_Zp[G_ * ZP_GSTRIDE];   // [g][bhp*8+sq][l]
__device__ float g_outp[G_ * OP_GSTRIDE]; // [g][sz][bh][rowG][d][row]
__device__ float g_heatp[G_ * HP_GSTRIDE];// [g][bp][h][s]
__device__ float g_distp[G_ * B_ * HEADS_ * SPLITS_];

typedef unsigned long long ull;

__device__ __forceinline__ void ffma2(ull& d, ull a, ull b)
{
    asm("fma.rn.f32x2 %0, %1, %2, %0;" : "+l"(d) : "l"(a), "l"(b));
}
__device__ __forceinline__ float2 unpk(ull v)
{
    float2 r;
    asm("mov.b64 {%0, %1}, %2;" : "=f"(r.x), "=f"(r.y) : "l"(v));
    return r;
}
__device__ __forceinline__ ull pack2(float v)
{
    ull r;
    asm("mov.b64 %0, {%1, %1};" : "=l"(r) : "f"(v));
    return r;
}
__device__ __forceinline__ void ld_bcast4(const float* p, ull* w)
{
    float4 b = *(const float4*)p;
    w[0] = pack2(b.x); w[1] = pack2(b.y); w[2] = pack2(b.z); w[3] = pack2(b.w);
}

// cp.async helpers
__device__ __forceinline__ void cpa16(void* smem, const void* g)
{
    unsigned a = (unsigned)__cvta_generic_to_shared(smem);
    asm volatile("cp.async.cg.shared.global [%0], [%1], 16;\n" :: "r"(a), "l"(g));
}
__device__ __forceinline__ void cpa_commit()
{
    asm volatile("cp.async.commit_group;\n");
}
__device__ __forceinline__ void cpa_wait1()
{
    asm volatile("cp.async.wait_group 1;\n");
}
__device__ __forceinline__ void cpa_wait0()
{
    asm volatile("cp.async.wait_group 0;\n");
}

// ---------------------------------------------------------------------------
// All projections in one launch.
// z < 96:  K/V proj. z = g*32 + dst*16 + batch.
// z >= 96: Q proj (only blockIdx.x == 0 works). zq = z-96 = g*8 + p.
// ---------------------------------------------------------------------------
__global__ __launch_bounds__(256, 3) void proj_all_kernel(
    const float* __restrict__ A, const float* __restrict__ protos,
    const float* __restrict__ Wk, const float* __restrict__ Wv,
    const float* __restrict__ Wq)
{
    extern __shared__ float sm[];
    int tid = threadIdx.x;
    int z = blockIdx.z;

    if (z >= 96) {                       // ---- Q projection path ----
        if (blockIdx.x != 0) return;
        int zq = z - 96;
        int g = zq >> 3, p = zq & 7;
        float* As = sm;                  // [32][68]
        float* Wd = sm + 32 * 68;        // [32][132] dup
        int txq = tid & 15, tyq = tid >> 4;
        int n0 = blockIdx.y * 64;
        const float* Ab = protos + (size_t)(g * SPLITS_ + p) * C_ * L_;
        const float* W = Wq + (size_t)g * C_ * INNER_;
        float* qg = g_Q + (size_t)g * Q_GSTRIDE;

        ull acc[4][2] = {};
        for (int c0 = 0; c0 < C_; c0 += 32) {
            __syncthreads();
            for (int idx = tid; idx < 512; idx += 256) {
                int c = idx >> 4, q = idx & 15;
                *(float4*)&As[c * 68 + q * 4] =
                    *(const float4*)&Ab[(size_t)(c0 + c) * L_ + q * 4];
                float4 w = *(const float4*)&W[(size_t)(c0 + c) * INNER_ + n0 + q * 4];
                float* wr = &Wd[c * 132 + q * 8];
                wr[0] = w.x; wr[1] = w.x; wr[2] = w.y; wr[3] = w.y;
                wr[4] = w.z; wr[5] = w.z; wr[6] = w.w; wr[7] = w.w;
            }
            __syncthreads();
            #pragma unroll
            for (int cc = 0; cc < 32; cc++) {
                ulonglong2 am  = *(ulonglong2*)&As[cc * 68 + txq * 4];
                ulonglong2 w01 = *(ulonglong2*)&Wd[cc * 132 + tyq * 8];
                ulonglong2 w23 = *(ulonglong2*)&Wd[cc * 132 + tyq * 8 + 4];
                ffma2(acc[0][0], w01.x, am.x); ffma2(acc[0][1], w01.x, am.y);
                ffma2(acc[1][0], w01.y, am.x); ffma2(acc[1][1], w01.y, am.y);
                ffma2(acc[2][0], w23.x, am.x); ffma2(acc[2][1], w23.x, am.y);
                ffma2(acc[3][0], w23.y, am.x); ffma2(acc[3][1], w23.y, am.y);
            }
        }
        #pragma unroll
        for (int i4 = 0; i4 < 4; i4++) {
            int n = n0 + tyq * 4 + i4;
            float2 a = unpk(acc[i4][0]), b2 = unpk(acc[i4][1]);
            int l = txq * 4;
            qg[((size_t)p * L_ + l + 0) * INNER_ + n] = a.x;
            qg[((size_t)p * L_ + l + 1) * INNER_ + n] = a.y;
            qg[((size_t)p * L_ + l + 2) * INNER_ + n] = b2.x;
            qg[((size_t)p * L_ + l + 3) * INNER_ + n] = b2.y;
        }
        return;
    }

    // ---- K/V projection path (R14 verbatim) ----
    float* As = sm;                  // [2][32][128]
    float* Ws = sm + 2 * 32 * 128;   // [2][32][68]
    int tx = tid & 31, wy = tid >> 5;
    int m0 = blockIdx.x * 128, n0 = blockIdx.y * 64;
    int g = z >> 5, r = z & 31;
    int dst = r >> 4, batch = r & 15;
    const float* W = (dst ? Wv : Wk) + (size_t)g * C_ * INNER_;
    const float* Ab = A + (size_t)batch * C_ * S_;

    ull acc[8][2] = {};
    for (int t = 0; t < 9; t++) {
        if (t < 8) {
            float* as = As + (t & 1) * 32 * 128;
            float* ws = Ws + (t & 1) * 32 * 68;
            int c0 = t * 32;
            #pragma unroll
            for (int it = 0; it < 4; it++) {
                int idx = tid + it * 256;
                int c = idx >> 5, f4 = idx & 31;
                cpa16(&as[c * 128 + f4 * 4],
                      &Ab[(size_t)(c0 + c) * S_ + m0 + f4 * 4]);
            }
            #pragma unroll
            for (int it = 0; it < 2; it++) {
                int idx = tid + it * 256;
                int c = idx >> 4, f4 = idx & 15;
                cpa16(&ws[c * 68 + f4 * 4],
                      &W[(size_t)(c0 + c) * INNER_ + n0 + f4 * 4]);
            }
            cpa_commit();
        }
        if (t == 0) continue;
        if (t < 8) cpa_wait1(); else cpa_wait0();
        __syncthreads();
        const float* as = As + ((t - 1) & 1) * 32 * 128;
        const float* ws = Ws + ((t - 1) & 1) * 32 * 68;
        #pragma unroll 4
        for (int c = 0; c < 32; c++) {
            ulonglong2 av = *(const ulonglong2*)&as[c * 128 + tx * 4];
            ull wp[4];
            ld_bcast4(&ws[c * 68 + wy * 8], wp);
            #pragma unroll
            for (int ni = 0; ni < 4; ni++) {
                ffma2(acc[ni][0], wp[ni], av.x);
                ffma2(acc[ni][1], wp[ni], av.y);
            }
            ld_bcast4(&ws[c * 68 + wy * 8 + 4], wp);
            #pragma unroll
            for (int ni = 0; ni < 4; ni++) {
                ffma2(acc[4 + ni][0], wp[ni], av.x);
                ffma2(acc[4 + ni][1], wp[ni], av.y);
            }
        }
        if (t < 8) __syncthreads();
    }

    if (dst == 0) {
        float* kg = g_K + (size_t)g * K_GSTRIDE;
        #pragma unroll
        for (int ni = 0; ni < 8; ni++) {
            int n = n0 + wy * 8 + ni;
            float2 f0 = unpk(acc[ni][0]), f1 = unpk(acc[ni][1]);
            *(float4*)&kg[((size_t)batch * INNER_ + n) * S_ + m0 + tx * 4] =
                make_float4(f0.x, f0.y, f1.x, f1.y);
        }
    } else {
        float* vg = g_V + (size_t)g * V_GSTRIDE;
        #pragma unroll
        for (int j = 0; j < 4; j++) {
            int m = m0 + tx * 4 + j;
            int sj = j >> 1, hi = j & 1;
            float v[8];
            #pragma unroll
            for (int ni = 0; ni < 8; ni++) {
                float2 f = unpk(acc[ni][sj]);
                v[ni] = hi ? f.y : f.x;
            }
            float* vr = &vg[((size_t)batch * S_ + m) * INNER_ + n0 + wy * 8];
            *(float4*)&vr[0] = make_float4(v[0], v[1], v[2], v[3]);
            *(float4*)&vr[4] = make_float4(v[4], v[5], v[6], v[7]);
        }
    }
}

// ---------------------------------------------------------------------------
// Scores, all groups: blockIdx.y = g*1024 + bhp. Grid (8, 3072). (R14)
// ---------------------------------------------------------------------------
__global__ __launch_bounds__(256, 3) void scores_kernel()
{
    extern __shared__ float sm[];
    float* Kt = sm;                  // [2][32][128]
    float* Qs = sm + 2 * 32 * 128;   // [64][68]  Qs[d][l]

    int sq = blockIdx.x;
    int y = blockIdx.y;
    int g = y >> 10, bhp = y & 1023;
    int p = bhp & 7, h = (bhp >> 3) & 7, b = bhp >> 6;
    int s0 = sq * 128;
    int tid = threadIdx.x;
    int tx = tid & 31, wy = tid >> 5;

    const float* kbase = g_K + (size_t)g * K_GSTRIDE +
                         ((size_t)(b * HEADS_ + h) * DH_) * S_ + s0;
    const float* qbase = g_Q + (size_t)g * Q_GSTRIDE +
                         (size_t)p * L_ * INNER_ + h * DH_;

    #pragma unroll
    for (int t = 0; t < 2; t++) {
        float* kt = Kt + t * 32 * 128;
        #pragma unroll
        for (int it = 0; it < 4; it++) {
            int idx = tid + it * 256;
            int d = idx >> 5, f4 = idx & 31;
            cpa16(&kt[d * 128 + f4 * 4],
                  &kbase[(size_t)(t * 32 + d) * S_ + f4 * 4]);
        }
        cpa_commit();
    }

    #pragma unroll
    for (int it = 0; it < 4; it++) {
        int idx = tid + it * 256;
        int dq = idx & 15, l = idx >> 4;
        float4 q = *(const float4*)&qbase[(size_t)l * INNER_ + dq * 4];
        Qs[(dq * 4 + 0) * 68 + l] = q.x;
        Qs[(dq * 4 + 1) * 68 + l] = q.y;
        Qs[(dq * 4 + 2) * 68 + l] = q.z;
        Qs[(dq * 4 + 3) * 68 + l] = q.w;
    }

    ull acc[8][2] = {};
    #pragma unroll
    for (int t = 0; t < 2; t++) {
        if (t == 0) cpa_wait1(); else cpa_wait0();
        __syncthreads();
        const float* kt = Kt + t * 32 * 128;
        #pragma unroll 4
        for (int d = 0; d < 32; d++) {
            ulonglong2 kv = *(const ulonglong2*)&kt[d * 128 + tx * 4];
            ull qp[4];
            ld_bcast4(&Qs[(t * 32 + d) * 68 + wy * 8], qp);
            #pragma unroll
            for (int li = 0; li < 4; li++) {
                ffma2(acc[li][0], qp[li], kv.x);
                ffma2(acc[li][1], qp[li], kv.y);
            }
            ld_bcast4(&Qs[(t * 32 + d) * 68 + wy * 8 + 4], qp);
            #pragma unroll
            for (int li = 0; li < 4; li++) {
                ffma2(acc[4 + li][0], qp[li], kv.x);
                ffma2(acc[4 + li][1], qp[li], kv.y);
            }
        }
    }

    float* eg = g_E + (size_t)g * E_GSTRIDE;
    float* zg = g_Zp + (size_t)g * ZP_GSTRIDE;
    #pragma unroll
    for (int li = 0; li < 8; li++) {
        int l = wy * 8 + li;
        float2 a0 = unpk(acc[li][0]), a1 = unpk(acc[li][1]);
        float e0 = __expf(a0.x * SCALE_), e1 = __expf(a0.y * SCALE_);
        float e2 = __expf(a1.x * SCALE_), e3 = __expf(a1.y * SCALE_);
        *(float4*)&eg[((size_t)bhp * L_ + l) * S_ + s0 + tx * 4] =
            make_float4(e0, e1, e2, e3);
        float z = (e0 + e1) + (e2 + e3);
        #pragma unroll
        for (int off = 16; off; off >>= 1)
            z += __shfl_xor_sync(0xffffffffu, z, off);
        if (tx == 0) zg[(bhp * 8 + sq) * 64 + l] = z;
    }
}

// ---------------------------------------------------------------------------
// Out slices (sz=4, R14): grid (4, 4, 384). invZ computed inline from Zp.
// ---------------------------------------------------------------------------
__global__ __launch_bounds__(256, 3) void out_slice_kernel()
{
    extern __shared__ float sm[];
    float* Es    = sm;                       // [32][132]  Es[s][row]
    float* Vs    = sm + 32 * 132;            // [32][68]   Vs[s][d]
    float* invZs = sm + 32 * 132 + 32 * 68;  // [128]

    int rowG = blockIdx.x;
    int sz   = blockIdx.y;
    int zz   = blockIdx.z;
    int g = zz >> 7, bh = zz & 127;
    int b = bh >> 3, h = bh & 7;
    int tid = threadIdx.x;
    int tx = tid & 31, wy = tid >> 5;

    if (tid < 128) {
        int p_loc = tid >> 6, l = tid & 63;
        int bhp = bh * 8 + rowG * 2 + p_loc;
        const float* zp = g_Zp + (size_t)g * ZP_GSTRIDE;
        float zsum = 0.f;
        #pragma unroll
        for (int j = 0; j < 8; j++) zsum += zp[((size_t)bhp * 8 + j) * 64 + l];
        invZs[tid] = 1.0f / zsum;
    }

    const float* vbase = g_V + (size_t)g * V_GSTRIDE +
                         (size_t)b * S_ * INNER_ + h * DH_;
    size_t ebase = (size_t)g * E_GSTRIDE +
                   (size_t)(bh * 8 + rowG * 2) * L_ * S_;

    ull acc[8][2] = {};
    for (int c = 0; c < 8; c++) {
        int s0 = sz * 256 + c * 32;
        __syncthreads();
        #pragma unroll
        for (int it = 0; it < 2; it++) {
            int idx = tid + it * 256;
            int f4 = idx & 15, s = idx >> 4;
            cpa16(&Vs[s * 68 + f4 * 4],
                  &vbase[(size_t)(s0 + s) * INNER_ + f4 * 4]);
        }
        cpa_commit();
        #pragma unroll
        for (int it = 0; it < 4; it++) {
            int idx = tid + it * 256;
            int sq4 = idx & 7, r = idx >> 3;
            float4 e = *(const float4*)&g_E[ebase + (size_t)r * S_ + s0 + sq4 * 4];
            Es[(sq4 * 4 + 0) * 132 + r] = e.x;
            Es[(sq4 * 4 + 1) * 132 + r] = e.y;
            Es[(sq4 * 4 + 2) * 132 + r] = e.z;
            Es[(sq4 * 4 + 3) * 132 + r] = e.w;
        }
        cpa_wait0();
        __syncthreads();

        #pragma unroll 4
        for (int s = 0; s < 32; s++) {
            ulonglong2 ev = *(const ulonglong2*)&Es[s * 132 + tx * 4];
            ull vp[4];
            ld_bcast4(&Vs[s * 68 + wy * 8], vp);
            #pragma unroll
            for (int di = 0; di < 4; di++) {
                ffma2(acc[di][0], vp[di], ev.x);
                ffma2(acc[di][1], vp[di], ev.y);
            }
            ld_bcast4(&Vs[s * 68 + wy * 8 + 4], vp);
            #pragma unroll
            for (int di = 0; di < 4; di++) {
                ffma2(acc[4 + di][0], vp[di], ev.x);
                ffma2(acc[4 + di][1], vp[di], ev.y);
            }
        }

        if (tid < 64) {
            int s_loc = tid & 31, p_loc = tid >> 5;
            float hacc = 0.f;
            #pragma unroll 16
            for (int l = 0; l < 64; l++)
                hacc += Es[s_loc * 132 + p_loc * 64 + l] * invZs[p_loc * 64 + l];
            int p = rowG * 2 + p_loc;
            g_heatp[(size_t)g * HP_GSTRIDE +
                    ((size_t)(b * SPLITS_ + p) * HEADS_ + h) * S_ + s0 + s_loc] = hacc;
        }
    }

    float* outBase = g_outp + (size_t)g * OP_GSTRIDE +
        (((size_t)(sz * 128 + bh) * 4 + rowG) * 64) * 128;
    #pragma unroll
    for (int di = 0; di < 8; di++) {
        int d = wy * 8 + di;
        float2 f0 = unpk(acc[di][0]), f1 = unpk(acc[di][1]);
        *(float4*)&outBase[(size_t)d * 128 + tx * 4] =
            make_float4(f0.x, f0.y, f1.x, f1.y);
    }
}

// ---------------------------------------------------------------------------
// Finale: blocks [0, 3072) = finish (dist partials, invZ inline);
//         blocks [3072, 3456) = argmax over summed heat partials.
// ---------------------------------------------------------------------------
__global__ void finale_kernel(float* __restrict__ out)
{
    int bid = blockIdx.x;
    int tid = threadIdx.x;

    if (bid < G_ * 1024) {               // ---- finish path ----
        int g = bid >> 10, bhp = bid & 1023;
        int p = bhp & 7, h = (bhp >> 3) & 7, b = bhp >> 6;
        int bh = b * 8 + h;
        int rowG = p >> 1, p_loc = p & 1;

        __shared__ float invz_s[64];
        if (tid < 64) {
            const float* zp = g_Zp + (size_t)g * ZP_GSTRIDE;
            float zsum = 0.f;
            #pragma unroll
            for (int j = 0; j < 8; j++)
                zsum += zp[((size_t)bhp * 8 + j) * 64 + tid];
            invz_s[tid] = 1.0f / zsum;
        }
        __syncthreads();

        const float* qb = g_Q + (size_t)g * Q_GSTRIDE +
                          (size_t)p * L_ * INNER_ + h * DH_;
        const float* op = g_outp + (size_t)g * OP_GSTRIDE;
        float ssum = 0.f;
        #pragma unroll
        for (int it = 0; it < 16; it++) {
            int idx = tid + it * 256;
            int d = idx >> 6, l = idx & 63;
            float v = 0.f;
            #pragma unroll
            for (int sz = 0; sz < 4; sz++)
                v += op[(((size_t)(sz * 128 + bh) * 4 + rowG) * 64 + d) * 128 +
                        p_loc * 64 + l];
            float o = v * invz_s[l];
            float diff = qb[(size_t)l * INNER_ + d] - o;
            ssum += diff * diff;
        }
        __shared__ float red[256];
        red[tid] = ssum;
        __syncthreads();
        for (int off = 128; off > 0; off >>= 1) {
            if (tid < off) red[tid] += red[tid + off];
            __syncthreads();
        }
        if (tid == 0) g_distp[bid] = red[0];
    } else {                             // ---- argmax path ----
        int a = bid - G_ * 1024;
        int g = a >> 7, bp = a & 127;
        int p = bp & 7, b = bp >> 3;
        const float* hp = g_heatp + (size_t)g * HP_GSTRIDE +
                          (size_t)bp * HEADS_ * S_;

        float best = -FLT_MAX;
        int bidx = 0;
        for (int s = tid; s < S_; s += 256) {
            float v = 0.f;
            #pragma unroll
            for (int h = 0; h < HEADS_; h++) v += hp[(size_t)h * S_ + s];
            if (v > best) { best = v; bidx = s; }
        }
        __shared__ float sv[256];
        __shared__ int si[256];
        sv[tid] = best; si[tid] = bidx;
        __syncthreads();
        for (int off = 128; off > 0; off >>= 1) {
            if (tid < off) {
                bool take = (sv[tid + off] > sv[tid]) ||
                            (sv[tid + off] == sv[tid] && si[tid + off] < si[tid]);
                if (take) { sv[tid] = sv[tid + off]; si[tid] = si[tid + off]; }
            }
            __syncthreads();
        }
        if (tid == 0) out[384 + b * 24 + g * 8 + p] = (float)si[0];
    }
}

// ---------------------------------------------------------------------------
__global__ void reduce_dist_kernel(float* __restrict__ out)
{
    int g = blockIdx.x;
    int t = threadIdx.x;
    if (t < B_ * SPLITS_) {
        int p = t & 7, b = t >> 3;
        float s = 0.f;
        #pragma unroll
        for (int h = 0; h < HEADS_; h++)
            s += g_distp[g * 1024 + b * 64 + h * 8 + p];
        out[b * 24 + g * 8 + p] = s * (1.0f / (L_ * INNER_));
    }
}

// ---------------------------------------------------------------------------
extern "C" void kernel_launch(void* const* d_in, const int* in_sizes, int n_in,
                              void* d_out, int out_size)
{
    const float* x      = (const float*)d_in[0];
    const float* protos = (const float*)d_in[1];
    const float* Wq     = (const float*)d_in[2];
    const float* Wk     = (const float*)d_in[3];
    const float* Wv     = (const float*)d_in[4];
    float* out = (float*)d_out;

    constexpr int PROJ_SMEM   = (2 * 32 * 128 + 2 * 32 * 68) * 4;    // 50176
    constexpr int SCORES_SMEM = (2 * 32 * 128 + 64 * 68) * 4;        // 50176
    constexpr int OUT_SMEM    = (32 * 132 + 32 * 68 + 128) * 4;      // 26112

    cudaFuncSetAttribute(proj_all_kernel,
                         cudaFuncAttributeMaxDynamicSharedMemorySize, PROJ_SMEM);
    cudaFuncSetAttribute(scores_kernel,
                         cudaFuncAttributeMaxDynamicSharedMemorySize, SCORES_SMEM);

    proj_all_kernel<<<dim3(S_ / 128, INNER_ / 64, 96 + G_ * SPLITS_), 256,
                      PROJ_SMEM>>>(x, protos, Wk, Wv, Wq);
    scores_kernel<<<dim3(8, G_ * 1024), 256, SCORES_SMEM>>>();
    out_slice_kernel<<<dim3(4, 4, G_ * 128), 256, OUT_SMEM>>>();
    finale_kernel<<<G_ * 1024 + G_ * 128, 256>>>(out);
    reduce_dist_kernel<<<G_, 128>>>(out);
}